// round 3
// baseline (speedup 1.0000x reference)
#include <cuda_runtime.h>
#include <math.h>

// Problem constants (N=128 images, P=16 control points, S=128 grid)
#define NIMG 128
#define NP   16
#define SDIM 128
#define RAD  6
#define KW   (2*RAD+1)        // 13-tap Gaussian (exp(-36) ~ 2e-16, negligible)
#define NT   512              // threads per block

// Shared layouts
#define ROWC (129 + 2*RAD)    // 141 histogram rows (x in 0..128, +halo)
#define COLC 132              // histogram cols padded (y in 0..128), mult of 4
#define ROWM 128              // M1 rows (s)
#define COLM 144              // M1 cols padded (need 141), mult of 4

#define SMEM_FLOATS (ROWC*COLC + ROWM*COLM)

__global__ __launch_bounds__(NT)
void plotline2_kernel(const float* __restrict__ points, float* __restrict__ out)
{
    extern __shared__ float sm[];
    float* cnt = sm;                    // [ROWC][COLC]
    float* m1  = sm + ROWC * COLC;      // [ROWM][COLM]

    const int n   = blockIdx.x;
    const int tid = threadIdx.x;

    // Gaussian taps: w[d'] = exp(-(d'-RAD)^2)
    float w[KW];
#pragma unroll
    for (int d = 0; d < KW; ++d) {
        int dd = d - RAD;
        w[d] = expf(-(float)(dd * dd));
    }

    // ---- zero shared (vectorized: both regions are 16B-aligned multiples of 4 floats) ----
    {
        float4* p4 = (float4*)sm;
        const int n4 = SMEM_FLOATS / 4;   // 9261
        float4 z = make_float4(0.f, 0.f, 0.f, 0.f);
        for (int i = tid; i < n4; i += NT) p4[i] = z;
    }
    __syncthreads();

    // ---- stage 1: histogram of rounded interpolated points ----
    // K = (P-1)*S = 1920 points: seg = k/128, step i = k%128, t = i/128
    const float inv = 1.0f / (float)SDIM;
    const float* pn = points + n * NP * 2;
    for (int k = tid; k < (NP - 1) * SDIM; k += NT) {
        int seg = k >> 7;
        int i   = k & 127;
        float t   = (float)i * inv;        // exact (i/128)
        float omt = 1.0f - t;              // exact
        float x0 = pn[seg * 2 + 0];
        float y0 = pn[seg * 2 + 1];
        float x1 = pn[seg * 2 + 2];
        float y1 = pn[seg * 2 + 3];
        // match XLA: mul, mul, add — no fma contraction
        float x = __fadd_rn(__fmul_rn(omt, x0), __fmul_rn(t, x1));
        float y = __fadd_rn(__fmul_rn(omt, y0), __fmul_rn(t, y1));
        int ix = (int)rintf(x);            // round-half-to-even, 0..128
        int iy = (int)rintf(y);
        atomicAdd(&cnt[(ix + RAD) * COLC + iy], 1.0f);
    }
    __syncthreads();

    // ---- stage 2: vertical (x) convolution ----
    // m1[s][y] = sum_{d'} w[d'] * cnt[s + d'][y],  s in 0..127, y in 0..128
    // 8-wide sliding window along s per thread: 20 loads -> 8 outputs
    for (int item = tid; item < 16 * 129; item += NT) {
        int sg = item / 129;               // s-group (0..15)
        int y  = item - sg * 129;          // 0..128
        int sbase = sg * 8;
        float v[8 + KW - 1];               // 20
#pragma unroll
        for (int j = 0; j < 8 + KW - 1; ++j)
            v[j] = cnt[(sbase + j) * COLC + y];
#pragma unroll
        for (int i = 0; i < 8; ++i) {
            float acc = 0.0f;
#pragma unroll
            for (int d = 0; d < KW; ++d)
                acc = fmaf(w[d], v[i + d], acc);
            m1[(sbase + i) * COLM + (y + RAD)] = acc;
        }
    }
    __syncthreads();

    // ---- stage 3: horizontal (y) convolution + tanh + store ----
    // out[s][t] = tanh( sum_{d'} w[d'] * m1[s][t + d'] )
    float* outn = out + (size_t)n * SDIM * SDIM;
    for (int item = tid; item < SDIM * 16; item += NT) {
        int s  = item >> 4;
        int tb = (item & 15) * 8;
        float v[8 + KW - 1];
#pragma unroll
        for (int j = 0; j < 8 + KW - 1; ++j)
            v[j] = m1[s * COLM + tb + j];
        float r[8];
#pragma unroll
        for (int i = 0; i < 8; ++i) {
            float acc = 0.0f;
#pragma unroll
            for (int d = 0; d < KW; ++d)
                acc = fmaf(w[d], v[i + d], acc);
            r[i] = tanhf(acc);
        }
        // vectorized store: 2x float4 per thread
        float4* dst = (float4*)(outn + s * SDIM + tb);
        dst[0] = make_float4(r[0], r[1], r[2], r[3]);
        dst[1] = make_float4(r[4], r[5], r[6], r[7]);
    }
}

extern "C" void kernel_launch(void* const* d_in, const int* in_sizes, int n_in,
                              void* d_out, int out_size)
{
    const float* points = (const float*)d_in[0];
    float* out = (float*)d_out;

    size_t smem = SMEM_FLOATS * sizeof(float);   // ~145 KB
    cudaFuncSetAttribute(plotline2_kernel,
                         cudaFuncAttributeMaxDynamicSharedMemorySize, (int)smem);
    plotline2_kernel<<<NIMG, NT, smem>>>(points, out);
}

// round 7
// speedup vs baseline: 1.0022x; 1.0022x over previous
#include <cuda_runtime.h>
#include <math.h>

// Problem constants (N=128 images, P=16 control points, S=128 grid)
#define NIMG 128
#define NP   16
#define SDIM 128
#define RAD  6
#define KW   (2*RAD+1)        // 13-tap Gaussian
#define NT   512

// Shared layouts
#define ROWC (129 + 2*RAD)    // 141 histogram rows (x in 0..128, +halo)
#define COLC 132              // histogram cols padded (y in 0..128), mult of 4
#define CNT_FLOATS (ROWC*COLC)            // 18612
#define COLM 141              // m1 pitch: 141 (needed) and 141%32=13 coprime -> conflict-free stride
#define M1_FLOATS (SDIM*COLM)             // 18048
#define RESP 129              // staging pitch (coprime with 32)

#define SMEM_FLOATS (CNT_FLOATS + M1_FLOATS)

__global__ __launch_bounds__(NT, 1)
void plotline2_kernel(const float* __restrict__ points, float* __restrict__ out)
{
    extern __shared__ float sm[];
    float* cnt = sm;                    // [ROWC][COLC]; later reused as res[128][RESP]
    float* m1  = sm + CNT_FLOATS;       // [SDIM][COLM]

    const int n   = blockIdx.x;
    const int tid = threadIdx.x;

    // Compile-time Gaussian taps -> FFMA immediates, no register pressure
    constexpr float W[KW] = {
        2.3195228302435696e-16f, 1.3887943864964021e-11f, 1.1253517471925912e-7f,
        1.2340980408667956e-4f,  0.018315638888734179f,   0.36787944117144233f,
        1.0f,
        0.36787944117144233f,    0.018315638888734179f,   1.2340980408667956e-4f,
        1.1253517471925912e-7f,  1.3887943864964021e-11f, 2.3195228302435696e-16f
    };

    // ---- zero cnt (full) + m1 halo columns only (stage 2 overwrites m1 interior) ----
    {
        float4* p4 = (float4*)cnt;
        float4 z = make_float4(0.f, 0.f, 0.f, 0.f);
        for (int i = tid; i < CNT_FLOATS / 4; i += NT) p4[i] = z;
        // m1 halo: cols 0..5 and 135..140 of every row
        for (int i = tid; i < SDIM * 2 * RAD; i += NT) {
            int r = i / (2 * RAD);
            int c = i - r * (2 * RAD);
            int col = (c < RAD) ? c : (COLM - 2 * RAD + c);   // 0..5 or 135..140
            m1[r * COLM + col] = 0.0f;
        }
    }
    __syncthreads();

    // ---- stage 1: histogram of rounded interpolated points ----
    const float inv = 1.0f / (float)SDIM;
    const float* pn = points + n * NP * 2;
    for (int k = tid; k < (NP - 1) * SDIM; k += NT) {
        int seg = k >> 7;
        int i   = k & 127;
        float t   = (float)i * inv;
        float omt = 1.0f - t;
        float x0 = pn[seg * 2 + 0];
        float y0 = pn[seg * 2 + 1];
        float x1 = pn[seg * 2 + 2];
        float y1 = pn[seg * 2 + 3];
        // match XLA: mul, mul, add — no fma contraction
        float x = __fadd_rn(__fmul_rn(omt, x0), __fmul_rn(t, x1));
        float y = __fadd_rn(__fmul_rn(omt, y0), __fmul_rn(t, y1));
        int ix = (int)rintf(x);            // round-half-to-even, 0..128
        int iy = (int)rintf(y);
        atomicAdd(&cnt[(ix + RAD) * COLC + iy], 1.0f);
    }
    __syncthreads();

    // ---- stage 2: vertical (x) convolution ----
    // m1[s][y+RAD] = sum_d W[d] * cnt[s+d][y]; consecutive lanes -> consecutive y (conflict-free)
    for (int item = tid; item < 16 * 129; item += NT) {
        int sg = item / 129;
        int y  = item - sg * 129;          // 0..128
        int sbase = sg * 8;
        float v[8 + KW - 1];
#pragma unroll
        for (int j = 0; j < 8 + KW - 1; ++j)
            v[j] = cnt[(sbase + j) * COLC + y];
#pragma unroll
        for (int i = 0; i < 8; ++i) {
            float acc = 0.0f;
#pragma unroll
            for (int d = 0; d < KW; ++d)
                acc = fmaf(W[d], v[i + d], acc);
            m1[(sbase + i) * COLM + (y + RAD)] = acc;
        }
    }
    __syncthreads();

    // ---- stage 3: horizontal (y) convolution + tanh -> staged in res (reuses cnt) ----
    // Consecutive lanes -> consecutive s; m1 row stride 141 (bank stride 13) -> conflict-free.
    float* res = cnt;   // [128][RESP]
    for (int item = tid; item < SDIM * 16; item += NT) {
        int s   = item & 127;
        int tb  = (item >> 7) * 8;
        float v[8 + KW - 1];
#pragma unroll
        for (int j = 0; j < 8 + KW - 1; ++j)
            v[j] = m1[s * COLM + tb + j];
#pragma unroll
        for (int i = 0; i < 8; ++i) {
            float acc = 0.0f;
#pragma unroll
            for (int d = 0; d < KW; ++d)
                acc = fmaf(W[d], v[i + d], acc);
            // tanh(x), x >= 0:  1 - 2/(e^{2x}+1); inf-safe for large x
            float e = __expf(2.0f * acc);
            res[s * RESP + tb + i] = 1.0f - __fdividef(2.0f, e + 1.0f);
        }
    }
    __syncthreads();

    // ---- stage 4: coalesced copy res -> gmem ----
    float* outn = out + (size_t)n * SDIM * SDIM;
    for (int idx = tid; idx < SDIM * SDIM; idx += NT) {
        int s = idx >> 7;
        int t = idx & 127;
        outn[idx] = res[s * RESP + t];
    }
}

extern "C" void kernel_launch(void* const* d_in, const int* in_sizes, int n_in,
                              void* d_out, int out_size)
{
    const float* points = (const float*)d_in[0];
    float* out = (float*)d_out;

    size_t smem = SMEM_FLOATS * sizeof(float);   // ~143 KB
    cudaFuncSetAttribute(plotline2_kernel,
                         cudaFuncAttributeMaxDynamicSharedMemorySize, (int)smem);
    plotline2_kernel<<<NIMG, NT, smem>>>(points, out);
}